// round 3
// baseline (speedup 1.0000x reference)
#include <cuda_runtime.h>

// out[b, H-1-h, w] = exp(EPS)*o[0] + sum_{d=1}^{D-1} (prod_{k<d}(1-o[k])) * o[d]
// o = clip(v, EPS, 1-EPS).
//
// Warp-per-segment layout: D=128 split into NSEG=8 segments of 16 slices.
// One CTA (256 threads, 8 warps) owns 32 consecutive float4-rays; warp w
// scans segment w. Every warp load is a contiguous 512B row chunk.
// Segment pairs (A,T) compose associatively A = A_lo + T_lo*A_hi,
// T = T_lo*T_hi; warp 0 folds the 8 pairs from shared memory and writes
// the (vertically flipped) output row.

#define EPSF      1e-5f
#define ONE_MEPS  (1.0f - 1e-5f)
#define EXP_EPS   1.0000100000500002f   // expf(1e-5f)

static __device__ __forceinline__ float clipv(float v) {
    return fminf(fmaxf(v, EPSF), ONE_MEPS);
}

__global__ void __launch_bounds__(256, 6)
eff_loss_kernel(const float* __restrict__ vox, float* __restrict__ out) {
    constexpr int D = 128, H = 128, W4 = 32;
    constexpr int DSTRIDE = H * W4;          // float4 stride per depth slice (4096)
    constexpr int NSEG = 8;
    constexpr int SEGD = D / NSEG;           // 16 slices per segment

    __shared__ float4 Asm[NSEG][32];
    __shared__ float4 Tsm[NSEG][32];

    int lane = threadIdx.x & 31;
    int seg  = threadIdx.x >> 5;             // warp id = segment id
    int ray  = blockIdx.x * 32 + lane;       // 32 consecutive float4-rays per CTA

    int w4 = ray & (W4 - 1);                 // = lane (base is 32-aligned)
    int h  = (ray >> 5) & (H - 1);
    int b  =  ray >> 12;

    const float4* p = reinterpret_cast<const float4*>(vox)
                    + (size_t)b * D * DSTRIDE
                    + (size_t)(seg * SEGD) * DSTRIDE
                    + (size_t)h * W4 + w4;

    // first slice of segment: weight exp(EPS) only for the global d=0 term
    float w0 = (seg == 0) ? EXP_EPS : 1.0f;
    float4 v0 = p[0];
    float ox = clipv(v0.x), oy = clipv(v0.y), oz = clipv(v0.z), ow = clipv(v0.w);
    float ax = w0 * ox, ay = w0 * oy, az = w0 * oz, aw = w0 * ow;
    float Tx = 1.0f, Ty = 1.0f, Tz = 1.0f, Tw = 1.0f;

    #pragma unroll
    for (int d = 1; d < SEGD; ++d) {
        float4 c = p[(size_t)d * DSTRIDE];
        float cx = clipv(c.x), cy = clipv(c.y), cz = clipv(c.z), cw = clipv(c.w);
        Tx *= (1.0f - ox);  Ty *= (1.0f - oy);
        Tz *= (1.0f - oz);  Tw *= (1.0f - ow);
        ax = fmaf(Tx, cx, ax);  ay = fmaf(Ty, cy, ay);
        az = fmaf(Tz, cz, az);  aw = fmaf(Tw, cw, aw);
        ox = cx; oy = cy; oz = cz; ow = cw;
    }
    // close the segment transmittance: include last element
    Tx *= (1.0f - ox);  Ty *= (1.0f - oy);
    Tz *= (1.0f - oz);  Tw *= (1.0f - ow);

    Asm[seg][lane] = make_float4(ax, ay, az, aw);
    Tsm[seg][lane] = make_float4(Tx, Ty, Tz, Tw);
    __syncthreads();

    if (seg == 0) {
        // fold segments 1..7 onto this warp's (A, T) registers
        #pragma unroll
        for (int s = 1; s < NSEG; ++s) {
            float4 As = Asm[s][lane];
            float4 Ts = Tsm[s][lane];
            ax = fmaf(Tx, As.x, ax);  ay = fmaf(Ty, As.y, ay);
            az = fmaf(Tz, As.z, az);  aw = fmaf(Tw, As.w, aw);
            Tx *= Ts.x;  Ty *= Ts.y;  Tz *= Ts.z;  Tw *= Ts.w;
        }
        // vertical flip: output row H-1-h (contiguous 512B store per warp)
        reinterpret_cast<float4*>(out)[(size_t)b * H * W4
                                       + (size_t)(H - 1 - h) * W4 + w4]
            = make_float4(ax, ay, az, aw);
    }
}

extern "C" void kernel_launch(void* const* d_in, const int* in_sizes, int n_in,
                              void* d_out, int out_size) {
    const float* vox = (const float*)d_in[0];
    float* out = (float*)d_out;
    constexpr int NBLOCK = 65536 / 32;   // 2048 CTAs, one per 32 float4-rays
    eff_loss_kernel<<<NBLOCK, 256>>>(vox, out);
}